// round 13
// baseline (speedup 1.0000x reference)
#include <cuda_runtime.h>
#include <cuda_bf16.h>
#include <stdint.h>
#include <math.h>
#include <string.h>

#define B_ROWS 65536
#define HID    1024
#define LAT    128
#define NITER  24

// out = concat(vecs[1,B,128], kld_exp[B], redundant_norm[B,1], mu[B,128])
#define OUT_VECS 0
#define OUT_KLD  (8388608)
#define OUT_RN   (8388608 + 65536)
#define OUT_MU   (8388608 + 131072)

__device__ float g_w[B_ROWS];
// Pre-split W: per 32-col chunk, [hi tile 10240B | lo tile 10240B], tile row pitch 80B
__device__ __align__(16) unsigned char g_Wsp[16][20480];

struct WKeys {
    uint32_t ka[NITER][2];
    uint32_t kb[NITER][2];
    uint32_t ku[NITER][2];
};

__host__ __device__ __forceinline__ uint32_t rotl32(uint32_t v, int r) {
    return (v << r) | (v >> (32 - r));
}

__host__ __device__ __forceinline__ void tf2x32(uint32_t k0, uint32_t k1,
                                                uint32_t x0, uint32_t x1,
                                                uint32_t& o0, uint32_t& o1) {
    uint32_t ks2 = k0 ^ k1 ^ 0x1BD11BDAu;
    x0 += k0; x1 += k1;
#define TFR(r) { x0 += x1; x1 = rotl32(x1, r); x1 ^= x0; }
    TFR(13) TFR(15) TFR(26) TFR(6)
    x0 += k1; x1 += ks2 + 1u;
    TFR(17) TFR(29) TFR(16) TFR(24)
    x0 += ks2; x1 += k0 + 2u;
    TFR(13) TFR(15) TFR(26) TFR(6)
    x0 += k0; x1 += k1 + 3u;
    TFR(17) TFR(29) TFR(16) TFR(24)
    x0 += k1; x1 += ks2 + 4u;
    TFR(13) TFR(15) TFR(26) TFR(6)
    x0 += ks2; x1 += k0 + 5u;
#undef TFR
    o0 = x0; o1 = x1;
}

__device__ __forceinline__ uint32_t rbits32(uint32_t k0, uint32_t k1, uint32_t i) {
    uint32_t b0, b1;
    tf2x32(k0, k1, 0u, i, b0, b1);
    return b0 ^ b1;
}

__device__ __forceinline__ float bits_to_unit(uint32_t bits) {
    return __uint_as_float((bits >> 9) | 0x3f800000u) - 1.0f;
}

// XLA f32 erfinv (Giles)
__device__ __forceinline__ float erfinv_f(float x) {
    float w = -log1pf(-x * x);
    float p;
    if (w < 5.0f) {
        w = w - 2.5f;
        p = 2.81022636e-08f;
        p = fmaf(p, w, 3.43273939e-07f);
        p = fmaf(p, w, -3.5233877e-06f);
        p = fmaf(p, w, -4.39150654e-06f);
        p = fmaf(p, w, 0.00021858087f);
        p = fmaf(p, w, -0.00125372503f);
        p = fmaf(p, w, -0.00417768164f);
        p = fmaf(p, w, 0.246640727f);
        p = fmaf(p, w, 1.50140941f);
    } else {
        w = sqrtf(w) - 3.0f;
        p = -0.000200214257f;
        p = fmaf(p, w, 0.000100950558f);
        p = fmaf(p, w, 0.00134934322f);
        p = fmaf(p, w, -0.00367342844f);
        p = fmaf(p, w, 0.00573950773f);
        p = fmaf(p, w, -0.0076224613f);
        p = fmaf(p, w, 0.00943887047f);
        p = fmaf(p, w, 1.00167406f);
        p = fmaf(p, w, 2.83297682f);
    }
    return p * x;
}

__device__ __forceinline__ float normal_scalar(uint32_t k0, uint32_t k1) {
    float f = bits_to_unit(rbits32(k0, k1, 0u));
    const float lo = -0.99999994f;
    float u = fmaxf(lo, fmaf(f, 2.0f, lo));
    return 1.41421356f * erfinv_f(u);
}

// Marsaglia-Tsang log-gamma(63.5), replicating jax._gamma_one key chain
__device__ float log_gamma_63(uint32_t k0, uint32_t k1) {
    const float dg = 63.5f - (1.0f / 3.0f);
    const float cg = (1.0f / 3.0f) / sqrtf(dg);
    uint32_t nk0, nk1;
    tf2x32(k0, k1, 0u, 0u, nk0, nk1);
    k0 = nk0; k1 = nk1;
    float V = 1.0f;
    #pragma unroll 1
    for (int it = 0; it < 40; ++it) {
        uint32_t c0, c1, xk0, xk1, uk0, uk1;
        tf2x32(k0, k1, 0u, 0u, c0, c1);
        tf2x32(k0, k1, 0u, 1u, xk0, xk1);
        tf2x32(k0, k1, 0u, 2u, uk0, uk1);
        k0 = c0; k1 = c1;
        float x = 0.0f, v = -1.0f;
        #pragma unroll 1
        for (int j = 0; j < 16; ++j) {
            uint32_t a0, a1, s0, s1;
            tf2x32(xk0, xk1, 0u, 0u, a0, a1);
            tf2x32(xk0, xk1, 0u, 1u, s0, s1);
            xk0 = a0; xk1 = a1;
            x = normal_scalar(s0, s1);
            v = fmaf(x, cg, 1.0f);
            if (v > 0.0f) break;
        }
        float X = x * x;
        V = v * v * v;
        float U = bits_to_unit(rbits32(uk0, uk1, 0u));
        bool rej = (U >= 1.0f - 0.0331f * (X * X)) &&
                   (logf(U) >= 0.5f * X + dg * ((1.0f - V) + logf(V)));
        if (!rej) break;
    }
    return logf(dg) + logf(V);
}

__global__ __launch_bounds__(256) void sample_w_kernel(
        WKeys K, float opb, float omb, float xf, float cf,
        const float* __restrict__ kld, float* __restrict__ out) {
    int i = blockIdx.x * blockDim.x + threadIdx.x;
    if (i >= B_ROWS) return;
    float w = 0.0f;
    #pragma unroll 1
    for (int t = 0; t < NITER; ++t) {
        uint32_t a0, a1, b0, b1;
        tf2x32(K.ka[t][0], K.ka[t][1], 0u, (uint32_t)i, a0, a1);
        float lga = log_gamma_63(a0, a1);
        tf2x32(K.kb[t][0], K.kb[t][1], 0u, (uint32_t)i, b0, b1);
        float lgb = log_gamma_63(b0, b1);
        float m  = fmaxf(lga, lgb);
        float ea = expf(lga - m), eb = expf(lgb - m);
        float z  = ea / (ea + eb);
        float wc = (1.0f - opb * z) / (1.0f - omb * z);
        float f  = bits_to_unit(rbits32(K.ku[t][0], K.ku[t][1], (uint32_t)i));
        float u  = fmaxf(1e-12f, f + 1e-12f);
        float acc = wc + 127.0f * logf(1.0f - xf * wc) - cf;
        if (acc >= logf(u)) { w = wc; break; }
    }
    g_w[i] = w;
    out[OUT_KLD + i] = kld[0];
}

// ------------------- helpers -------------------
#define TILE_B   10240       // one sub-tile: 128 rows x 40 bf16 (80B rows)
#define STAGE_B  40960
#define SM_TOTAL 81920       // 2 stages -> 2 CTAs/SM
#define CSTRIDE  132

__device__ __forceinline__ uint32_t smem_u32(const void* p) {
    uint32_t a;
    asm("{ .reg .u64 t; cvta.to.shared.u64 t, %1; cvt.u32.u64 %0, t; }" : "=r"(a) : "l"(p));
    return a;
}

__device__ __forceinline__ void ldsm4(uint32_t* r, uint32_t a) {
    asm volatile("ldmatrix.sync.aligned.m8n8.x4.shared.b16 {%0,%1,%2,%3}, [%4];"
                 : "=r"(r[0]), "=r"(r[1]), "=r"(r[2]), "=r"(r[3]) : "r"(a));
}
__device__ __forceinline__ void mma_bf16(float* c, const uint32_t* a, const uint32_t* b) {
    asm volatile(
        "mma.sync.aligned.m16n8k16.row.col.f32.bf16.bf16.f32 "
        "{%0,%1,%2,%3}, {%4,%5,%6,%7}, {%8,%9}, {%0,%1,%2,%3};"
        : "+f"(c[0]), "+f"(c[1]), "+f"(c[2]), "+f"(c[3])
        : "r"(a[0]), "r"(a[1]), "r"(a[2]), "r"(a[3]), "r"(b[0]), "r"(b[1]));
}

__device__ __forceinline__ void split2(float x, float y, uint32_t& hi, uint32_t& lo) {
    __nv_bfloat16 hx = __float2bfloat16_rn(x);
    __nv_bfloat16 hy = __float2bfloat16_rn(y);
    __nv_bfloat16 lx = __float2bfloat16_rn(x - __bfloat162float(hx));
    __nv_bfloat16 ly = __float2bfloat16_rn(y - __bfloat162float(hy));
    uint16_t a, b;
    memcpy(&a, &hx, 2); memcpy(&b, &hy, 2);
    hi = (uint32_t)a | ((uint32_t)b << 16);
    memcpy(&a, &lx, 2); memcpy(&b, &ly, 2);
    lo = (uint32_t)a | ((uint32_t)b << 16);
}

__device__ __forceinline__ void cpasync16(uint32_t dst, const void* src) {
    asm volatile("cp.async.cg.shared.global [%0], [%1], 16;" :: "r"(dst), "l"(src));
}

// ------------------- W pre-split kernel -------------------
__global__ __launch_bounds__(256) void w_split_kernel2(const float* __restrict__ W) {
    int idx = blockIdx.x * blockDim.x + threadIdx.x;   // 32768 float4s
    if (idx >= 32768) return;
    int r = idx >> 8;            // row 0..127
    int g = idx & 255;           // quad within row, 0..255
    int c = g >> 3;              // chunk 0..15
    int q = g & 7;               // quad within chunk
    float4 v = __ldg((const float4*)(W + (size_t)r * HID + g * 4));
    uint32_t h0, l0, h1, l1;
    split2(v.x, v.y, h0, l0);
    split2(v.z, v.w, h1, l1);
    uint32_t off = (uint32_t)(r * 80 + q * 8);
    *(uint2*)(g_Wsp[c] + off)         = make_uint2(h0, h1);
    *(uint2*)(g_Wsp[c] + 10240 + off) = make_uint2(l0, l1);
}

// ------------------- GEMM + normalize + fused vecs (no extra smem) -------------------
__global__ __launch_bounds__(256, 1) void gemm_tc_kernel(
        const float* __restrict__ A, const float* __restrict__ bias,
        float* __restrict__ out, uint32_t kv0, uint32_t kv1) {
    extern __shared__ __align__(16) unsigned char sm[];
    const int tid = threadIdx.x;
    const int lane = tid & 31, wid = tid >> 5;
    const int wm = wid & 3, wn = wid >> 2;     // 4 x 2 warp grid; warp tile 32x64
    const size_t m0 = (size_t)blockIdx.x * 128;
    const float* Ab = A + m0 * HID;
    const uint32_t smb = smem_u32(sm);

    float acc[2][8][4];
    #pragma unroll
    for (int i = 0; i < 2; ++i)
        #pragma unroll
        for (int j = 0; j < 8; ++j)
            #pragma unroll
            for (int k = 0; k < 4; ++k) acc[i][j][k] = 0.0f;

    float4 ra[4];

    auto LOAD = [&](int c) {
        int k0 = c * 32;
        #pragma unroll
        for (int i = 0; i < 4; ++i) {
            int flat = i * 256 + tid;
            int r = flat >> 3, q = flat & 7;
            ra[i] = __ldg((const float4*)(Ab + (size_t)r * HID + k0 + q * 4));
        }
    };

    auto STORE = [&](int s) {
        unsigned char* base = sm + s * STAGE_B;
        #pragma unroll
        for (int i = 0; i < 4; ++i) {
            int flat = i * 256 + tid;
            int r = flat >> 3, q = flat & 7;
            uint32_t off = (uint32_t)(r * 80 + q * 8);
            uint32_t h0, l0, h1, l1;
            split2(ra[i].x, ra[i].y, h0, l0);
            split2(ra[i].z, ra[i].w, h1, l1);
            *(uint2*)(base + off)          = make_uint2(h0, h1);
            *(uint2*)(base + TILE_B + off) = make_uint2(l0, l1);
        }
    };

    auto ISSUEW = [&](int c, int s) {
        const unsigned char* src = g_Wsp[c];
        uint32_t dst = smb + s * STAGE_B + 2 * TILE_B;
        #pragma unroll
        for (int i = 0; i < 5; ++i) {
            int idx = i * 256 + tid;           // 1280 x 16B = 20480B (hi|lo)
            cpasync16(dst + idx * 16, src + idx * 16);
        }
        asm volatile("cp.async.commit_group;" ::: "memory");
    };

    auto COMPUTE = [&](int s) {
        uint32_t base = smb + s * STAGE_B;
        #pragma unroll
        for (int kk = 0; kk < 2; ++kk) {
            uint32_t ahi[2][4], alo[2][4];
            #pragma unroll
            for (int mi = 0; mi < 2; ++mi) {
                uint32_t ad = base + (uint32_t)((wm * 32 + mi * 16 + (lane & 15)) * 80
                                                + kk * 32 + (lane >> 4) * 16);
                ldsm4(ahi[mi], ad);
                ldsm4(alo[mi], ad + TILE_B);
            }
            uint32_t bhi[8][2], blo[8][2];
            #pragma unroll
            for (int nq = 0; nq < 4; ++nq) {
                uint32_t nrow = (uint32_t)(wn * 64 + nq * 16 + (lane & 7) + ((lane >> 4) & 1) * 8);
                uint32_t bd = base + 2 * TILE_B
                            + nrow * 80 + (uint32_t)(kk * 32 + ((lane >> 3) & 1) * 16);
                uint32_t r[4];
                ldsm4(r, bd);
                bhi[nq * 2][0] = r[0]; bhi[nq * 2][1] = r[1];
                bhi[nq * 2 + 1][0] = r[2]; bhi[nq * 2 + 1][1] = r[3];
                ldsm4(r, bd + TILE_B);
                blo[nq * 2][0] = r[0]; blo[nq * 2][1] = r[1];
                blo[nq * 2 + 1][0] = r[2]; blo[nq * 2 + 1][1] = r[3];
            }
            #pragma unroll
            for (int mi = 0; mi < 2; ++mi)
                #pragma unroll
                for (int ni = 0; ni < 8; ++ni) {
                    mma_bf16(acc[mi][ni], ahi[mi], bhi[ni]);
                    mma_bf16(acc[mi][ni], ahi[mi], blo[ni]);
                    mma_bf16(acc[mi][ni], alo[mi], bhi[ni]);
                }
        }
    };

    LOAD(0);
    ISSUEW(0, 0);
    STORE(0);
    asm volatile("cp.async.wait_group 0;" ::: "memory");
    __syncthreads();
    #pragma unroll 1
    for (int c = 0; c < 32; ++c) {
        if (c < 31) { LOAD(c + 1); ISSUEW(c + 1, (c + 1) & 1); }
        COMPUTE(c & 1);
        if (c < 31) {
            STORE((c + 1) & 1);
            asm volatile("cp.async.wait_group 0;" ::: "memory");
        }
        __syncthreads();
    }

    // ---- epilogue ----
    float* C   = (float*)sm;                       // [128][CSTRIDE]
    float* P   = (float*)(sm + 128 * CSTRIDE * 4); // 256 partials
    float* INV = P + 256;                          // 128 inv-norms
    float* WM  = INV + 128;                        // 128 w values
    #pragma unroll
    for (int mi = 0; mi < 2; ++mi)
        #pragma unroll
        for (int ni = 0; ni < 8; ++ni) {
            int r = wm * 32 + mi * 16 + (lane >> 2);
            int cc = wn * 64 + ni * 8 + (lane & 3) * 2;
            float b0 = __ldg(bias + cc), b1 = __ldg(bias + cc + 1);
            C[r * CSTRIDE + cc]           = acc[mi][ni][0] + b0;
            C[r * CSTRIDE + cc + 1]       = acc[mi][ni][1] + b1;
            C[(r + 8) * CSTRIDE + cc]     = acc[mi][ni][2] + b0;
            C[(r + 8) * CSTRIDE + cc + 1] = acc[mi][ni][3] + b1;
        }
    __syncthreads();
    {
        int row = tid >> 1, h = tid & 1;
        const float4* rp = (const float4*)(C + row * CSTRIDE + h * 64);
        float s = 0.0f;
        #pragma unroll
        for (int j = 0; j < 16; ++j) {
            float4 v = rp[j];
            s = fmaf(v.x, v.x, s); s = fmaf(v.y, v.y, s);
            s = fmaf(v.z, v.z, s); s = fmaf(v.w, v.w, s);
        }
        P[tid] = s;
    }
    __syncthreads();
    if (tid < 128) {
        float s = P[2 * tid] + P[2 * tid + 1];
        float nrm = sqrtf(s);
        float dn = nrm - 1.0f;
        out[OUT_RN + m0 + tid] = dn * dn;
        INV[tid] = 1.0f / nrm;
        WM[tid]  = g_w[m0 + tid];
    }
    __syncthreads();
    #pragma unroll 4
    for (int idx = tid; idx < 4096; idx += 256) {
        int row = idx >> 5, c4 = idx & 31;
        float inv = INV[row];
        float4 v = *(const float4*)(C + row * CSTRIDE + c4 * 4);
        v.x *= inv; v.y *= inv; v.z *= inv; v.w *= inv;
        *(float4*)(out + OUT_MU + (m0 + row) * 128 + c4 * 4) = v;
    }

    // ---- fused vecs: each warp processes 16 rows, zero extra smem ----
    #pragma unroll 1
    for (int rr = 0; rr < 16; ++rr) {
        int row = wid * 16 + rr;
        float inv = INV[row];
        float m[4], v[4];
        float dot = 0.0f;
        const float lo = -0.99999994f;
        uint32_t base_i = (uint32_t)((m0 + row) * 128);
        #pragma unroll
        for (int q = 0; q < 4; ++q) {
            int col = lane + 32 * q;
            m[q] = C[row * CSTRIDE + col] * inv;
            float f = bits_to_unit(rbits32(kv0, kv1, base_i + (uint32_t)col));
            float u = fmaxf(lo, fmaf(f, 2.0f, lo));
            v[q] = 1.41421356f * erfinv_f(u);
            dot = fmaf(m[q], v[q], dot);
        }
        #pragma unroll
        for (int s = 16; s; s >>= 1) dot += __shfl_xor_sync(0xffffffffu, dot, s);
        float o[4];
        float n2 = 0.0f;
        #pragma unroll
        for (int q = 0; q < 4; ++q) {
            o[q] = v[q] - m[q] * dot;
            n2 = fmaf(o[q], o[q], n2);
        }
        #pragma unroll
        for (int s = 16; s; s >>= 1) n2 += __shfl_xor_sync(0xffffffffu, n2, s);
        float invn = 1.0f / sqrtf(n2);
        float w = WM[row];
        float s1 = sqrtf(1.0f - w * w);
        #pragma unroll
        for (int q = 0; q < 4; ++q)
            out[OUT_VECS + (m0 + (size_t)row) * 128 + lane + 32 * q]
                = o[q] * invn * s1 + m[q] * w;
    }
}

extern "C" void kernel_launch(void* const* d_in, const int* in_sizes, int n_in,
                              void* d_out, int out_size) {
    const float* lat_code = (const float*)d_in[0];
    const float* W_mu     = (const float*)d_in[1];
    const float* b_mu     = (const float*)d_in[2];
    const float* kld      = (const float*)d_in[3];
    float* out = (float*)d_out;

    // Host-side threefry key chains (partitionable semantics)
    uint32_t f0, f1;
    tf2x32(0u, 42u, 0u, 0u, f0, f1);
    uint32_t kw0, kw1, kv0, kv1;
    tf2x32(f0, f1, 0u, 0u, kw0, kw1);
    tf2x32(f0, f1, 0u, 1u, kv0, kv1);

    WKeys K;
    uint32_t c0 = kw0, c1 = kw1;
    for (int t = 0; t < NITER; ++t) {
        uint32_t n0, n1, k1a, k1b, k2a, k2b;
        tf2x32(c0, c1, 0u, 0u, n0, n1);
        tf2x32(c0, c1, 0u, 1u, k1a, k1b);
        tf2x32(c0, c1, 0u, 2u, k2a, k2b);
        tf2x32(k1a, k1b, 0u, 0u, K.ka[t][0], K.ka[t][1]);
        tf2x32(k1a, k1b, 0u, 1u, K.kb[t][0], K.kb[t][1]);
        K.ku[t][0] = k2a; K.ku[t][1] = k2b;
        c0 = n0; c1 = n1;
    }

    double dd = 127.0, kap = 1.0;
    double bb = dd / (sqrt(4.0 * kap * kap + dd * dd) + 2.0 * kap);
    double xx = (1.0 - bb) / (1.0 + bb);
    double cc = kap * xx + dd * log(1.0 - xx * xx);
    float opb = (float)(1.0 + bb), omb = (float)(1.0 - bb);
    float xf = (float)xx, cf = (float)cc;

    cudaFuncSetAttribute(gemm_tc_kernel,
                         cudaFuncAttributeMaxDynamicSharedMemorySize, SM_TOTAL);

    w_split_kernel2<<<128, 256>>>(W_mu);
    sample_w_kernel<<<B_ROWS / 256, 256>>>(K, opb, omb, xf, cf, kld, out);
    gemm_tc_kernel<<<B_ROWS / 128, 256, SM_TOTAL>>>(lat_code, b_mu, out, kv0, kv1);
}

// round 15
// speedup vs baseline: 1.1573x; 1.1573x over previous
#include <cuda_runtime.h>
#include <cuda_bf16.h>
#include <stdint.h>
#include <math.h>
#include <string.h>

#define B_ROWS 65536
#define HID    1024
#define LAT    128
#define NITER  24

// out = concat(vecs[1,B,128], kld_exp[B], redundant_norm[B,1], mu[B,128])
#define OUT_VECS 0
#define OUT_KLD  (8388608)
#define OUT_RN   (8388608 + 65536)
#define OUT_MU   (8388608 + 131072)

__device__ float g_w[B_ROWS];
// Pre-split W: per 32-col chunk, [hi tile 10240B | lo tile 10240B], tile row pitch 80B
__device__ __align__(16) unsigned char g_Wsp[16][20480];

struct WKeys {
    uint32_t ka[NITER][2];
    uint32_t kb[NITER][2];
    uint32_t ku[NITER][2];
};

__host__ __device__ __forceinline__ uint32_t rotl32(uint32_t v, int r) {
    return (v << r) | (v >> (32 - r));
}

__host__ __device__ __forceinline__ void tf2x32(uint32_t k0, uint32_t k1,
                                                uint32_t x0, uint32_t x1,
                                                uint32_t& o0, uint32_t& o1) {
    uint32_t ks2 = k0 ^ k1 ^ 0x1BD11BDAu;
    x0 += k0; x1 += k1;
#define TFR(r) { x0 += x1; x1 = rotl32(x1, r); x1 ^= x0; }
    TFR(13) TFR(15) TFR(26) TFR(6)
    x0 += k1; x1 += ks2 + 1u;
    TFR(17) TFR(29) TFR(16) TFR(24)
    x0 += ks2; x1 += k0 + 2u;
    TFR(13) TFR(15) TFR(26) TFR(6)
    x0 += k0; x1 += k1 + 3u;
    TFR(17) TFR(29) TFR(16) TFR(24)
    x0 += k1; x1 += ks2 + 4u;
    TFR(13) TFR(15) TFR(26) TFR(6)
    x0 += ks2; x1 += k0 + 5u;
#undef TFR
    o0 = x0; o1 = x1;
}

__device__ __forceinline__ uint32_t rbits32(uint32_t k0, uint32_t k1, uint32_t i) {
    uint32_t b0, b1;
    tf2x32(k0, k1, 0u, i, b0, b1);
    return b0 ^ b1;
}

__device__ __forceinline__ float bits_to_unit(uint32_t bits) {
    return __uint_as_float((bits >> 9) | 0x3f800000u) - 1.0f;
}

// XLA f32 erfinv (Giles)
__device__ __forceinline__ float erfinv_f(float x) {
    float w = -log1pf(-x * x);
    float p;
    if (w < 5.0f) {
        w = w - 2.5f;
        p = 2.81022636e-08f;
        p = fmaf(p, w, 3.43273939e-07f);
        p = fmaf(p, w, -3.5233877e-06f);
        p = fmaf(p, w, -4.39150654e-06f);
        p = fmaf(p, w, 0.00021858087f);
        p = fmaf(p, w, -0.00125372503f);
        p = fmaf(p, w, -0.00417768164f);
        p = fmaf(p, w, 0.246640727f);
        p = fmaf(p, w, 1.50140941f);
    } else {
        w = sqrtf(w) - 3.0f;
        p = -0.000200214257f;
        p = fmaf(p, w, 0.000100950558f);
        p = fmaf(p, w, 0.00134934322f);
        p = fmaf(p, w, -0.00367342844f);
        p = fmaf(p, w, 0.00573950773f);
        p = fmaf(p, w, -0.0076224613f);
        p = fmaf(p, w, 0.00943887047f);
        p = fmaf(p, w, 1.00167406f);
        p = fmaf(p, w, 2.83297682f);
    }
    return p * x;
}

__device__ __forceinline__ float normal_scalar(uint32_t k0, uint32_t k1) {
    float f = bits_to_unit(rbits32(k0, k1, 0u));
    const float lo = -0.99999994f;
    float u = fmaxf(lo, fmaf(f, 2.0f, lo));
    return 1.41421356f * erfinv_f(u);
}

// Marsaglia-Tsang log-gamma(63.5), replicating jax._gamma_one key chain
__device__ float log_gamma_63(uint32_t k0, uint32_t k1) {
    const float dg = 63.5f - (1.0f / 3.0f);
    const float cg = (1.0f / 3.0f) / sqrtf(dg);
    uint32_t nk0, nk1;
    tf2x32(k0, k1, 0u, 0u, nk0, nk1);
    k0 = nk0; k1 = nk1;
    float V = 1.0f;
    #pragma unroll 1
    for (int it = 0; it < 40; ++it) {
        uint32_t c0, c1, xk0, xk1, uk0, uk1;
        tf2x32(k0, k1, 0u, 0u, c0, c1);
        tf2x32(k0, k1, 0u, 1u, xk0, xk1);
        tf2x32(k0, k1, 0u, 2u, uk0, uk1);
        k0 = c0; k1 = c1;
        float x = 0.0f, v = -1.0f;
        #pragma unroll 1
        for (int j = 0; j < 16; ++j) {
            uint32_t a0, a1, s0, s1;
            tf2x32(xk0, xk1, 0u, 0u, a0, a1);
            tf2x32(xk0, xk1, 0u, 1u, s0, s1);
            xk0 = a0; xk1 = a1;
            x = normal_scalar(s0, s1);
            v = fmaf(x, cg, 1.0f);
            if (v > 0.0f) break;
        }
        float X = x * x;
        V = v * v * v;
        float U = bits_to_unit(rbits32(uk0, uk1, 0u));
        bool rej = (U >= 1.0f - 0.0331f * (X * X)) &&
                   (logf(U) >= 0.5f * X + dg * ((1.0f - V) + logf(V)));
        if (!rej) break;
    }
    return logf(dg) + logf(V);
}

__global__ __launch_bounds__(256) void sample_w_kernel(
        WKeys K, float opb, float omb, float xf, float cf,
        const float* __restrict__ kld, float* __restrict__ out) {
    int i = blockIdx.x * blockDim.x + threadIdx.x;
    if (i >= B_ROWS) return;
    float w = 0.0f;
    #pragma unroll 1
    for (int t = 0; t < NITER; ++t) {
        uint32_t a0, a1, b0, b1;
        tf2x32(K.ka[t][0], K.ka[t][1], 0u, (uint32_t)i, a0, a1);
        float lga = log_gamma_63(a0, a1);
        tf2x32(K.kb[t][0], K.kb[t][1], 0u, (uint32_t)i, b0, b1);
        float lgb = log_gamma_63(b0, b1);
        float m  = fmaxf(lga, lgb);
        float ea = expf(lga - m), eb = expf(lgb - m);
        float z  = ea / (ea + eb);
        float wc = (1.0f - opb * z) / (1.0f - omb * z);
        float f  = bits_to_unit(rbits32(K.ku[t][0], K.ku[t][1], (uint32_t)i));
        float u  = fmaxf(1e-12f, f + 1e-12f);
        float acc = wc + 127.0f * logf(1.0f - xf * wc) - cf;
        if (acc >= logf(u)) { w = wc; break; }
    }
    g_w[i] = w;
    out[OUT_KLD + i] = kld[0];
}

// ------------------- helpers -------------------
#define TILE_B   10240       // one sub-tile: 128 rows x 40 bf16 (80B rows)
#define STAGE_B  40960
#define SM_TOTAL 81920       // 2 stages -> 2 CTAs/SM
#define CSTRIDE  132

__device__ __forceinline__ uint32_t smem_u32(const void* p) {
    uint32_t a;
    asm("{ .reg .u64 t; cvta.to.shared.u64 t, %1; cvt.u32.u64 %0, t; }" : "=r"(a) : "l"(p));
    return a;
}

__device__ __forceinline__ void ldsm4(uint32_t* r, uint32_t a) {
    asm volatile("ldmatrix.sync.aligned.m8n8.x4.shared.b16 {%0,%1,%2,%3}, [%4];"
                 : "=r"(r[0]), "=r"(r[1]), "=r"(r[2]), "=r"(r[3]) : "r"(a));
}
__device__ __forceinline__ void mma_bf16(float* c, const uint32_t* a, const uint32_t* b) {
    asm volatile(
        "mma.sync.aligned.m16n8k16.row.col.f32.bf16.bf16.f32 "
        "{%0,%1,%2,%3}, {%4,%5,%6,%7}, {%8,%9}, {%0,%1,%2,%3};"
        : "+f"(c[0]), "+f"(c[1]), "+f"(c[2]), "+f"(c[3])
        : "r"(a[0]), "r"(a[1]), "r"(a[2]), "r"(a[3]), "r"(b[0]), "r"(b[1]));
}

__device__ __forceinline__ void split2(float x, float y, uint32_t& hi, uint32_t& lo) {
    __nv_bfloat16 hx = __float2bfloat16_rn(x);
    __nv_bfloat16 hy = __float2bfloat16_rn(y);
    __nv_bfloat16 lx = __float2bfloat16_rn(x - __bfloat162float(hx));
    __nv_bfloat16 ly = __float2bfloat16_rn(y - __bfloat162float(hy));
    uint16_t a, b;
    memcpy(&a, &hx, 2); memcpy(&b, &hy, 2);
    hi = (uint32_t)a | ((uint32_t)b << 16);
    memcpy(&a, &lx, 2); memcpy(&b, &ly, 2);
    lo = (uint32_t)a | ((uint32_t)b << 16);
}

__device__ __forceinline__ void cpasync16(uint32_t dst, const void* src) {
    asm volatile("cp.async.cg.shared.global [%0], [%1], 16;" :: "r"(dst), "l"(src));
}

// ------------------- W pre-split kernel -------------------
__global__ __launch_bounds__(256) void w_split_kernel2(const float* __restrict__ W) {
    int idx = blockIdx.x * blockDim.x + threadIdx.x;   // 32768 float4s
    if (idx >= 32768) return;
    int r = idx >> 8;            // row 0..127
    int g = idx & 255;           // quad within row, 0..255
    int c = g >> 3;              // chunk 0..15
    int q = g & 7;               // quad within chunk
    float4 v = __ldg((const float4*)(W + (size_t)r * HID + g * 4));
    uint32_t h0, l0, h1, l1;
    split2(v.x, v.y, h0, l0);
    split2(v.z, v.w, h1, l1);
    uint32_t off = (uint32_t)(r * 80 + q * 8);
    *(uint2*)(g_Wsp[c] + off)         = make_uint2(h0, h1);
    *(uint2*)(g_Wsp[c] + 10240 + off) = make_uint2(l0, l1);
}

// ------------------- GEMM + normalize -------------------
__global__ __launch_bounds__(256, 1) void gemm_tc_kernel(
        const float* __restrict__ A, const float* __restrict__ bias,
        float* __restrict__ out) {
    extern __shared__ __align__(16) unsigned char sm[];
    const int tid = threadIdx.x;
    const int lane = tid & 31, wid = tid >> 5;
    const int wm = wid & 3, wn = wid >> 2;     // 4 x 2 warp grid; warp tile 32x64
    const size_t m0 = (size_t)blockIdx.x * 128;
    const float* Ab = A + m0 * HID;
    const uint32_t smb = smem_u32(sm);

    float acc[2][8][4];
    #pragma unroll
    for (int i = 0; i < 2; ++i)
        #pragma unroll
        for (int j = 0; j < 8; ++j)
            #pragma unroll
            for (int k = 0; k < 4; ++k) acc[i][j][k] = 0.0f;

    float4 ra[4];

    auto LOAD = [&](int c) {
        int k0 = c * 32;
        #pragma unroll
        for (int i = 0; i < 4; ++i) {
            int flat = i * 256 + tid;
            int r = flat >> 3, q = flat & 7;
            ra[i] = __ldg((const float4*)(Ab + (size_t)r * HID + k0 + q * 4));
        }
    };

    auto STORE = [&](int s) {
        unsigned char* base = sm + s * STAGE_B;
        #pragma unroll
        for (int i = 0; i < 4; ++i) {
            int flat = i * 256 + tid;
            int r = flat >> 3, q = flat & 7;
            uint32_t off = (uint32_t)(r * 80 + q * 8);
            uint32_t h0, l0, h1, l1;
            split2(ra[i].x, ra[i].y, h0, l0);
            split2(ra[i].z, ra[i].w, h1, l1);
            *(uint2*)(base + off)          = make_uint2(h0, h1);
            *(uint2*)(base + TILE_B + off) = make_uint2(l0, l1);
        }
    };

    auto ISSUEW = [&](int c, int s) {
        const unsigned char* src = g_Wsp[c];
        uint32_t dst = smb + s * STAGE_B + 2 * TILE_B;
        #pragma unroll
        for (int i = 0; i < 5; ++i) {
            int idx = i * 256 + tid;           // 1280 x 16B = 20480B (hi|lo)
            cpasync16(dst + idx * 16, src + idx * 16);
        }
        asm volatile("cp.async.commit_group;" ::: "memory");
    };

    auto COMPUTE = [&](int s) {
        uint32_t base = smb + s * STAGE_B;
        #pragma unroll
        for (int kk = 0; kk < 2; ++kk) {
            uint32_t ahi[2][4], alo[2][4];
            #pragma unroll
            for (int mi = 0; mi < 2; ++mi) {
                uint32_t ad = base + (uint32_t)((wm * 32 + mi * 16 + (lane & 15)) * 80
                                                + kk * 32 + (lane >> 4) * 16);
                ldsm4(ahi[mi], ad);
                ldsm4(alo[mi], ad + TILE_B);
            }
            uint32_t bhi[8][2], blo[8][2];
            #pragma unroll
            for (int nq = 0; nq < 4; ++nq) {
                uint32_t nrow = (uint32_t)(wn * 64 + nq * 16 + (lane & 7) + ((lane >> 4) & 1) * 8);
                uint32_t bd = base + 2 * TILE_B
                            + nrow * 80 + (uint32_t)(kk * 32 + ((lane >> 3) & 1) * 16);
                uint32_t r[4];
                ldsm4(r, bd);
                bhi[nq * 2][0] = r[0]; bhi[nq * 2][1] = r[1];
                bhi[nq * 2 + 1][0] = r[2]; bhi[nq * 2 + 1][1] = r[3];
                ldsm4(r, bd + TILE_B);
                blo[nq * 2][0] = r[0]; blo[nq * 2][1] = r[1];
                blo[nq * 2 + 1][0] = r[2]; blo[nq * 2 + 1][1] = r[3];
            }
            #pragma unroll
            for (int mi = 0; mi < 2; ++mi)
                #pragma unroll
                for (int ni = 0; ni < 8; ++ni) {
                    mma_bf16(acc[mi][ni], ahi[mi], bhi[ni]);
                    mma_bf16(acc[mi][ni], ahi[mi], blo[ni]);
                    mma_bf16(acc[mi][ni], alo[mi], bhi[ni]);
                }
        }
    };

    LOAD(0);
    ISSUEW(0, 0);
    STORE(0);
    asm volatile("cp.async.wait_group 0;" ::: "memory");
    __syncthreads();
    #pragma unroll 1
    for (int c = 0; c < 32; ++c) {
        if (c < 31) { LOAD(c + 1); ISSUEW(c + 1, (c + 1) & 1); }
        COMPUTE(c & 1);
        if (c < 31) {
            STORE((c + 1) & 1);
            asm volatile("cp.async.wait_group 0;" ::: "memory");
        }
        __syncthreads();
    }

    // ---- epilogue ----
    float* C   = (float*)sm;                       // [128][CSTRIDE]
    float* P   = (float*)(sm + 128 * CSTRIDE * 4); // 256 partials
    float* INV = P + 256;                          // 128 inv-norms
    #pragma unroll
    for (int mi = 0; mi < 2; ++mi)
        #pragma unroll
        for (int ni = 0; ni < 8; ++ni) {
            int r = wm * 32 + mi * 16 + (lane >> 2);
            int cc = wn * 64 + ni * 8 + (lane & 3) * 2;
            float b0 = __ldg(bias + cc), b1 = __ldg(bias + cc + 1);
            C[r * CSTRIDE + cc]           = acc[mi][ni][0] + b0;
            C[r * CSTRIDE + cc + 1]       = acc[mi][ni][1] + b1;
            C[(r + 8) * CSTRIDE + cc]     = acc[mi][ni][2] + b0;
            C[(r + 8) * CSTRIDE + cc + 1] = acc[mi][ni][3] + b1;
        }
    __syncthreads();
    {
        int row = tid >> 1, h = tid & 1;
        const float4* rp = (const float4*)(C + row * CSTRIDE + h * 64);
        float s = 0.0f;
        #pragma unroll
        for (int j = 0; j < 16; ++j) {
            float4 v = rp[j];
            s = fmaf(v.x, v.x, s); s = fmaf(v.y, v.y, s);
            s = fmaf(v.z, v.z, s); s = fmaf(v.w, v.w, s);
        }
        P[tid] = s;
    }
    __syncthreads();
    if (tid < 128) {
        float s = P[2 * tid] + P[2 * tid + 1];
        float nrm = sqrtf(s);
        float dn = nrm - 1.0f;
        out[OUT_RN + m0 + tid] = dn * dn;
        INV[tid] = 1.0f / nrm;
    }
    __syncthreads();
    #pragma unroll 4
    for (int idx = tid; idx < 4096; idx += 256) {
        int row = idx >> 5, c4 = idx & 31;
        float inv = INV[row];
        float4 v = *(const float4*)(C + row * CSTRIDE + c4 * 4);
        v.x *= inv; v.y *= inv; v.z *= inv; v.w *= inv;
        *(float4*)(out + OUT_MU + (m0 + row) * 128 + c4 * 4) = v;
    }
}

__global__ __launch_bounds__(256) void vecs_kernel(uint32_t kv0, uint32_t kv1,
                                                   float* __restrict__ out) {
    int warp = (int)((blockIdx.x * blockDim.x + threadIdx.x) >> 5);
    int lane = threadIdx.x & 31;
    if (warp >= B_ROWS) return;
    const float* mu = out + OUT_MU + (size_t)warp * 128;
    float m[4], v[4];
    float dot = 0.0f;
    #pragma unroll
    for (int q = 0; q < 4; ++q) {
        int col = lane + 32 * q;
        m[q] = mu[col];
        float f = bits_to_unit(rbits32(kv0, kv1, (uint32_t)(warp * 128 + col)));
        const float lo = -0.99999994f;
        float u = fmaxf(lo, fmaf(f, 2.0f, lo));
        v[q] = 1.41421356f * erfinv_f(u);
        dot = fmaf(m[q], v[q], dot);
    }
    #pragma unroll
    for (int s = 16; s; s >>= 1) dot += __shfl_xor_sync(0xffffffffu, dot, s);
    float o[4];
    float n2 = 0.0f;
    #pragma unroll
    for (int q = 0; q < 4; ++q) {
        o[q] = v[q] - m[q] * dot;
        n2 = fmaf(o[q], o[q], n2);
    }
    #pragma unroll
    for (int s = 16; s; s >>= 1) n2 += __shfl_xor_sync(0xffffffffu, n2, s);
    float inv = 1.0f / sqrtf(n2);
    float w = g_w[warp];
    float s1 = sqrtf(1.0f - w * w);
    #pragma unroll
    for (int q = 0; q < 4; ++q)
        out[OUT_VECS + (size_t)warp * 128 + lane + 32 * q] = o[q] * inv * s1 + m[q] * w;
}

extern "C" void kernel_launch(void* const* d_in, const int* in_sizes, int n_in,
                              void* d_out, int out_size) {
    const float* lat_code = (const float*)d_in[0];
    const float* W_mu     = (const float*)d_in[1];
    const float* b_mu     = (const float*)d_in[2];
    const float* kld      = (const float*)d_in[3];
    float* out = (float*)d_out;

    // Host-side threefry key chains (partitionable semantics)
    uint32_t f0, f1;
    tf2x32(0u, 42u, 0u, 0u, f0, f1);
    uint32_t kw0, kw1, kv0, kv1;
    tf2x32(f0, f1, 0u, 0u, kw0, kw1);
    tf2x32(f0, f1, 0u, 1u, kv0, kv1);

    WKeys K;
    uint32_t c0 = kw0, c1 = kw1;
    for (int t = 0; t < NITER; ++t) {
        uint32_t n0, n1, k1a, k1b, k2a, k2b;
        tf2x32(c0, c1, 0u, 0u, n0, n1);
        tf2x32(c0, c1, 0u, 1u, k1a, k1b);
        tf2x32(c0, c1, 0u, 2u, k2a, k2b);
        tf2x32(k1a, k1b, 0u, 0u, K.ka[t][0], K.ka[t][1]);
        tf2x32(k1a, k1b, 0u, 1u, K.kb[t][0], K.kb[t][1]);
        K.ku[t][0] = k2a; K.ku[t][1] = k2b;
        c0 = n0; c1 = n1;
    }

    double dd = 127.0, kap = 1.0;
    double bb = dd / (sqrt(4.0 * kap * kap + dd * dd) + 2.0 * kap);
    double xx = (1.0 - bb) / (1.0 + bb);
    double cc = kap * xx + dd * log(1.0 - xx * xx);
    float opb = (float)(1.0 + bb), omb = (float)(1.0 - bb);
    float xf = (float)xx, cf = (float)cc;

    cudaFuncSetAttribute(gemm_tc_kernel,
                         cudaFuncAttributeMaxDynamicSharedMemorySize, SM_TOTAL);

    // Fork-join: sample_w runs concurrent with w_split + GEMM; join before vecs.
    cudaStream_t s2;
    cudaEvent_t e_fork, e_join;
    bool forked = (cudaStreamCreateWithFlags(&s2, cudaStreamNonBlocking) == cudaSuccess) &&
                  (cudaEventCreateWithFlags(&e_fork, cudaEventDisableTiming) == cudaSuccess) &&
                  (cudaEventCreateWithFlags(&e_join, cudaEventDisableTiming) == cudaSuccess);

    if (forked) {
        cudaEventRecord(e_fork, 0);
        cudaStreamWaitEvent(s2, e_fork, 0);
        sample_w_kernel<<<B_ROWS / 256, 256, 0, s2>>>(K, opb, omb, xf, cf, kld, out);
        cudaEventRecord(e_join, s2);

        w_split_kernel2<<<128, 256>>>(W_mu);
        gemm_tc_kernel<<<B_ROWS / 128, 256, SM_TOTAL>>>(lat_code, b_mu, out);

        cudaStreamWaitEvent(0, e_join, 0);
        vecs_kernel<<<(B_ROWS * 32) / 256, 256>>>(kv0, kv1, out);

        cudaEventDestroy(e_fork);
        cudaEventDestroy(e_join);
        cudaStreamDestroy(s2);
    } else {
        // Fallback: serial schedule (R11)
        w_split_kernel2<<<128, 256>>>(W_mu);
        sample_w_kernel<<<B_ROWS / 256, 256>>>(K, opb, omb, xf, cf, kld, out);
        gemm_tc_kernel<<<B_ROWS / 128, 256, SM_TOTAL>>>(lat_code, b_mu, out);
        vecs_kernel<<<(B_ROWS * 32) / 256, 256>>>(kv0, kv1, out);
    }
}

// round 16
// speedup vs baseline: 1.3056x; 1.1281x over previous
#include <cuda_runtime.h>
#include <cuda_bf16.h>
#include <stdint.h>
#include <math.h>
#include <string.h>

#define B_ROWS 65536
#define HID    1024
#define LAT    128
#define NITER  24

// out = concat(vecs[1,B,128], kld_exp[B], redundant_norm[B,1], mu[B,128])
#define OUT_VECS 0
#define OUT_KLD  (8388608)
#define OUT_RN   (8388608 + 65536)
#define OUT_MU   (8388608 + 131072)

__device__ float g_w[B_ROWS];
// Pre-split W: per 32-col chunk, [hi tile 10240B | lo tile 10240B], tile row pitch 80B
__device__ __align__(16) unsigned char g_Wsp[16][20480];

struct WKeys {
    uint32_t ka[NITER][2];
    uint32_t kb[NITER][2];
    uint32_t ku[NITER][2];
};

__host__ __device__ __forceinline__ uint32_t rotl32(uint32_t v, int r) {
    return (v << r) | (v >> (32 - r));
}

__host__ __device__ __forceinline__ void tf2x32(uint32_t k0, uint32_t k1,
                                                uint32_t x0, uint32_t x1,
                                                uint32_t& o0, uint32_t& o1) {
    uint32_t ks2 = k0 ^ k1 ^ 0x1BD11BDAu;
    x0 += k0; x1 += k1;
#define TFR(r) { x0 += x1; x1 = rotl32(x1, r); x1 ^= x0; }
    TFR(13) TFR(15) TFR(26) TFR(6)
    x0 += k1; x1 += ks2 + 1u;
    TFR(17) TFR(29) TFR(16) TFR(24)
    x0 += ks2; x1 += k0 + 2u;
    TFR(13) TFR(15) TFR(26) TFR(6)
    x0 += k0; x1 += k1 + 3u;
    TFR(17) TFR(29) TFR(16) TFR(24)
    x0 += k1; x1 += ks2 + 4u;
    TFR(13) TFR(15) TFR(26) TFR(6)
    x0 += ks2; x1 += k0 + 5u;
#undef TFR
    o0 = x0; o1 = x1;
}

__device__ __forceinline__ uint32_t rbits32(uint32_t k0, uint32_t k1, uint32_t i) {
    uint32_t b0, b1;
    tf2x32(k0, k1, 0u, i, b0, b1);
    return b0 ^ b1;
}

__device__ __forceinline__ float bits_to_unit(uint32_t bits) {
    return __uint_as_float((bits >> 9) | 0x3f800000u) - 1.0f;
}

// XLA f32 erfinv (Giles)
__device__ __forceinline__ float erfinv_f(float x) {
    float w = -log1pf(-x * x);
    float p;
    if (w < 5.0f) {
        w = w - 2.5f;
        p = 2.81022636e-08f;
        p = fmaf(p, w, 3.43273939e-07f);
        p = fmaf(p, w, -3.5233877e-06f);
        p = fmaf(p, w, -4.39150654e-06f);
        p = fmaf(p, w, 0.00021858087f);
        p = fmaf(p, w, -0.00125372503f);
        p = fmaf(p, w, -0.00417768164f);
        p = fmaf(p, w, 0.246640727f);
        p = fmaf(p, w, 1.50140941f);
    } else {
        w = sqrtf(w) - 3.0f;
        p = -0.000200214257f;
        p = fmaf(p, w, 0.000100950558f);
        p = fmaf(p, w, 0.00134934322f);
        p = fmaf(p, w, -0.00367342844f);
        p = fmaf(p, w, 0.00573950773f);
        p = fmaf(p, w, -0.0076224613f);
        p = fmaf(p, w, 0.00943887047f);
        p = fmaf(p, w, 1.00167406f);
        p = fmaf(p, w, 2.83297682f);
    }
    return p * x;
}

__device__ __forceinline__ float normal_scalar(uint32_t k0, uint32_t k1) {
    float f = bits_to_unit(rbits32(k0, k1, 0u));
    const float lo = -0.99999994f;
    float u = fmaxf(lo, fmaf(f, 2.0f, lo));
    return 1.41421356f * erfinv_f(u);
}

// Marsaglia-Tsang log-gamma(63.5), replicating jax._gamma_one key chain
__device__ float log_gamma_63(uint32_t k0, uint32_t k1) {
    const float dg = 63.5f - (1.0f / 3.0f);
    const float cg = (1.0f / 3.0f) / sqrtf(dg);
    uint32_t nk0, nk1;
    tf2x32(k0, k1, 0u, 0u, nk0, nk1);
    k0 = nk0; k1 = nk1;
    float V = 1.0f;
    #pragma unroll 1
    for (int it = 0; it < 40; ++it) {
        uint32_t c0, c1, xk0, xk1, uk0, uk1;
        tf2x32(k0, k1, 0u, 0u, c0, c1);
        tf2x32(k0, k1, 0u, 1u, xk0, xk1);
        tf2x32(k0, k1, 0u, 2u, uk0, uk1);
        k0 = c0; k1 = c1;
        float x = 0.0f, v = -1.0f;
        #pragma unroll 1
        for (int j = 0; j < 16; ++j) {
            uint32_t a0, a1, s0, s1;
            tf2x32(xk0, xk1, 0u, 0u, a0, a1);
            tf2x32(xk0, xk1, 0u, 1u, s0, s1);
            xk0 = a0; xk1 = a1;
            x = normal_scalar(s0, s1);
            v = fmaf(x, cg, 1.0f);
            if (v > 0.0f) break;
        }
        float X = x * x;
        V = v * v * v;
        float U = bits_to_unit(rbits32(uk0, uk1, 0u));
        bool rej = (U >= 1.0f - 0.0331f * (X * X)) &&
                   (logf(U) >= 0.5f * X + dg * ((1.0f - V) + logf(V)));
        if (!rej) break;
    }
    return logf(dg) + logf(V);
}

__global__ __launch_bounds__(256) void sample_w_kernel(
        WKeys K, float opb, float omb, float xf, float cf,
        const float* __restrict__ kld, float* __restrict__ out) {
    int i = blockIdx.x * blockDim.x + threadIdx.x;
    if (i >= B_ROWS) return;
    float w = 0.0f;
    #pragma unroll 1
    for (int t = 0; t < NITER; ++t) {
        uint32_t a0, a1, b0, b1;
        tf2x32(K.ka[t][0], K.ka[t][1], 0u, (uint32_t)i, a0, a1);
        float lga = log_gamma_63(a0, a1);
        tf2x32(K.kb[t][0], K.kb[t][1], 0u, (uint32_t)i, b0, b1);
        float lgb = log_gamma_63(b0, b1);
        float m  = fmaxf(lga, lgb);
        float ea = expf(lga - m), eb = expf(lgb - m);
        float z  = ea / (ea + eb);
        float wc = (1.0f - opb * z) / (1.0f - omb * z);
        float f  = bits_to_unit(rbits32(K.ku[t][0], K.ku[t][1], (uint32_t)i));
        float u  = fmaxf(1e-12f, f + 1e-12f);
        float acc = wc + 127.0f * logf(1.0f - xf * wc) - cf;
        if (acc >= logf(u)) { w = wc; break; }
    }
    g_w[i] = w;
    out[OUT_KLD + i] = kld[0];
}

// ------------------- helpers -------------------
#define TILE_B   10240       // one sub-tile: 128 rows x 40 bf16 (80B rows)
#define STAGE_B  40960
#define SM_TOTAL 81920       // 2 stages -> 2 CTAs/SM
#define CSTRIDE  132

__device__ __forceinline__ uint32_t smem_u32(const void* p) {
    uint32_t a;
    asm("{ .reg .u64 t; cvta.to.shared.u64 t, %1; cvt.u32.u64 %0, t; }" : "=r"(a) : "l"(p));
    return a;
}

__device__ __forceinline__ void ldsm4(uint32_t* r, uint32_t a) {
    asm volatile("ldmatrix.sync.aligned.m8n8.x4.shared.b16 {%0,%1,%2,%3}, [%4];"
                 : "=r"(r[0]), "=r"(r[1]), "=r"(r[2]), "=r"(r[3]) : "r"(a));
}
__device__ __forceinline__ void mma_bf16(float* c, const uint32_t* a, const uint32_t* b) {
    asm volatile(
        "mma.sync.aligned.m16n8k16.row.col.f32.bf16.bf16.f32 "
        "{%0,%1,%2,%3}, {%4,%5,%6,%7}, {%8,%9}, {%0,%1,%2,%3};"
        : "+f"(c[0]), "+f"(c[1]), "+f"(c[2]), "+f"(c[3])
        : "r"(a[0]), "r"(a[1]), "r"(a[2]), "r"(a[3]), "r"(b[0]), "r"(b[1]));
}

__device__ __forceinline__ void split2(float x, float y, uint32_t& hi, uint32_t& lo) {
    __nv_bfloat16 hx = __float2bfloat16_rn(x);
    __nv_bfloat16 hy = __float2bfloat16_rn(y);
    __nv_bfloat16 lx = __float2bfloat16_rn(x - __bfloat162float(hx));
    __nv_bfloat16 ly = __float2bfloat16_rn(y - __bfloat162float(hy));
    uint16_t a, b;
    memcpy(&a, &hx, 2); memcpy(&b, &hy, 2);
    hi = (uint32_t)a | ((uint32_t)b << 16);
    memcpy(&a, &lx, 2); memcpy(&b, &ly, 2);
    lo = (uint32_t)a | ((uint32_t)b << 16);
}

__device__ __forceinline__ void cpasync16(uint32_t dst, const void* src) {
    asm volatile("cp.async.cg.shared.global [%0], [%1], 16;" :: "r"(dst), "l"(src));
}

// ------------------- W pre-split kernel -------------------
__global__ __launch_bounds__(256) void w_split_kernel2(const float* __restrict__ W) {
    int idx = blockIdx.x * blockDim.x + threadIdx.x;   // 32768 float4s
    if (idx >= 32768) return;
    int r = idx >> 8;            // row 0..127
    int g = idx & 255;           // quad within row, 0..255
    int c = g >> 3;              // chunk 0..15
    int q = g & 7;               // quad within chunk
    float4 v = __ldg((const float4*)(W + (size_t)r * HID + g * 4));
    uint32_t h0, l0, h1, l1;
    split2(v.x, v.y, h0, l0);
    split2(v.z, v.w, h1, l1);
    uint32_t off = (uint32_t)(r * 80 + q * 8);
    *(uint2*)(g_Wsp[c] + off)         = make_uint2(h0, h1);
    *(uint2*)(g_Wsp[c] + 10240 + off) = make_uint2(l0, l1);
}

// ------------------- GEMM + normalize + fused vecs, reg-capped for 2 CTAs/SM ----
__global__ __launch_bounds__(256, 2) void gemm_tc_kernel(
        const float* __restrict__ A, const float* __restrict__ bias,
        float* __restrict__ out, uint32_t kv0, uint32_t kv1) {
    extern __shared__ __align__(16) unsigned char sm[];
    const int tid = threadIdx.x;
    const int lane = tid & 31, wid = tid >> 5;
    const int wm = wid & 3, wn = wid >> 2;     // 4 x 2 warp grid; warp tile 32x64
    const size_t m0 = (size_t)blockIdx.x * 128;
    const float* Ab = A + m0 * HID;
    const uint32_t smb = smem_u32(sm);

    float acc[2][8][4];
    #pragma unroll
    for (int i = 0; i < 2; ++i)
        #pragma unroll
        for (int j = 0; j < 8; ++j)
            #pragma unroll
            for (int k = 0; k < 4; ++k) acc[i][j][k] = 0.0f;

    float4 ra[4];

    auto LOAD = [&](int c) {
        int k0 = c * 32;
        #pragma unroll
        for (int i = 0; i < 4; ++i) {
            int flat = i * 256 + tid;
            int r = flat >> 3, q = flat & 7;
            ra[i] = __ldg((const float4*)(Ab + (size_t)r * HID + k0 + q * 4));
        }
    };

    auto STORE = [&](int s) {
        unsigned char* base = sm + s * STAGE_B;
        #pragma unroll
        for (int i = 0; i < 4; ++i) {
            int flat = i * 256 + tid;
            int r = flat >> 3, q = flat & 7;
            uint32_t off = (uint32_t)(r * 80 + q * 8);
            uint32_t h0, l0, h1, l1;
            split2(ra[i].x, ra[i].y, h0, l0);
            split2(ra[i].z, ra[i].w, h1, l1);
            *(uint2*)(base + off)          = make_uint2(h0, h1);
            *(uint2*)(base + TILE_B + off) = make_uint2(l0, l1);
        }
    };

    auto ISSUEW = [&](int c, int s) {
        const unsigned char* src = g_Wsp[c];
        uint32_t dst = smb + s * STAGE_B + 2 * TILE_B;
        #pragma unroll
        for (int i = 0; i < 5; ++i) {
            int idx = i * 256 + tid;           // 1280 x 16B = 20480B (hi|lo)
            cpasync16(dst + idx * 16, src + idx * 16);
        }
        asm volatile("cp.async.commit_group;" ::: "memory");
    };

    auto COMPUTE = [&](int s) {
        uint32_t base = smb + s * STAGE_B;
        #pragma unroll
        for (int kk = 0; kk < 2; ++kk) {
            uint32_t ahi[2][4], alo[2][4];
            #pragma unroll
            for (int mi = 0; mi < 2; ++mi) {
                uint32_t ad = base + (uint32_t)((wm * 32 + mi * 16 + (lane & 15)) * 80
                                                + kk * 32 + (lane >> 4) * 16);
                ldsm4(ahi[mi], ad);
                ldsm4(alo[mi], ad + TILE_B);
            }
            uint32_t bhi[8][2], blo[8][2];
            #pragma unroll
            for (int nq = 0; nq < 4; ++nq) {
                uint32_t nrow = (uint32_t)(wn * 64 + nq * 16 + (lane & 7) + ((lane >> 4) & 1) * 8);
                uint32_t bd = base + 2 * TILE_B
                            + nrow * 80 + (uint32_t)(kk * 32 + ((lane >> 3) & 1) * 16);
                uint32_t r[4];
                ldsm4(r, bd);
                bhi[nq * 2][0] = r[0]; bhi[nq * 2][1] = r[1];
                bhi[nq * 2 + 1][0] = r[2]; bhi[nq * 2 + 1][1] = r[3];
                ldsm4(r, bd + TILE_B);
                blo[nq * 2][0] = r[0]; blo[nq * 2][1] = r[1];
                blo[nq * 2 + 1][0] = r[2]; blo[nq * 2 + 1][1] = r[3];
            }
            #pragma unroll
            for (int mi = 0; mi < 2; ++mi)
                #pragma unroll
                for (int ni = 0; ni < 8; ++ni) {
                    mma_bf16(acc[mi][ni], ahi[mi], bhi[ni]);
                    mma_bf16(acc[mi][ni], ahi[mi], blo[ni]);
                    mma_bf16(acc[mi][ni], alo[mi], bhi[ni]);
                }
        }
    };

    LOAD(0);
    ISSUEW(0, 0);
    STORE(0);
    asm volatile("cp.async.wait_group 0;" ::: "memory");
    __syncthreads();
    #pragma unroll 1
    for (int c = 0; c < 32; ++c) {
        if (c < 31) { LOAD(c + 1); ISSUEW(c + 1, (c + 1) & 1); }
        COMPUTE(c & 1);
        if (c < 31) {
            STORE((c + 1) & 1);
            asm volatile("cp.async.wait_group 0;" ::: "memory");
        }
        __syncthreads();
    }

    // ---- epilogue ----
    float* C   = (float*)sm;                       // [128][CSTRIDE]
    float* P   = (float*)(sm + 128 * CSTRIDE * 4); // 256 partials
    float* INV = P + 256;                          // 128 inv-norms
    float* WM  = INV + 128;                        // 128 w values
    #pragma unroll
    for (int mi = 0; mi < 2; ++mi)
        #pragma unroll
        for (int ni = 0; ni < 8; ++ni) {
            int r = wm * 32 + mi * 16 + (lane >> 2);
            int cc = wn * 64 + ni * 8 + (lane & 3) * 2;
            float b0 = __ldg(bias + cc), b1 = __ldg(bias + cc + 1);
            C[r * CSTRIDE + cc]           = acc[mi][ni][0] + b0;
            C[r * CSTRIDE + cc + 1]       = acc[mi][ni][1] + b1;
            C[(r + 8) * CSTRIDE + cc]     = acc[mi][ni][2] + b0;
            C[(r + 8) * CSTRIDE + cc + 1] = acc[mi][ni][3] + b1;
        }
    __syncthreads();
    {
        int row = tid >> 1, h = tid & 1;
        const float4* rp = (const float4*)(C + row * CSTRIDE + h * 64);
        float s = 0.0f;
        #pragma unroll
        for (int j = 0; j < 16; ++j) {
            float4 v = rp[j];
            s = fmaf(v.x, v.x, s); s = fmaf(v.y, v.y, s);
            s = fmaf(v.z, v.z, s); s = fmaf(v.w, v.w, s);
        }
        P[tid] = s;
    }
    __syncthreads();
    if (tid < 128) {
        float s = P[2 * tid] + P[2 * tid + 1];
        float nrm = sqrtf(s);
        float dn = nrm - 1.0f;
        out[OUT_RN + m0 + tid] = dn * dn;
        INV[tid] = 1.0f / nrm;
        WM[tid]  = g_w[m0 + tid];
    }
    __syncthreads();
    #pragma unroll 4
    for (int idx = tid; idx < 4096; idx += 256) {
        int row = idx >> 5, c4 = idx & 31;
        float inv = INV[row];
        float4 v = *(const float4*)(C + row * CSTRIDE + c4 * 4);
        v.x *= inv; v.y *= inv; v.z *= inv; v.w *= inv;
        *(float4*)(out + OUT_MU + (m0 + row) * 128 + c4 * 4) = v;
    }

    // ---- fused vecs: each warp processes 16 rows, zero extra smem ----
    #pragma unroll 1
    for (int rr = 0; rr < 16; ++rr) {
        int row = wid * 16 + rr;
        float inv = INV[row];
        float m[4], v[4];
        float dot = 0.0f;
        const float lo = -0.99999994f;
        uint32_t base_i = (uint32_t)((m0 + row) * 128);
        #pragma unroll
        for (int q = 0; q < 4; ++q) {
            int col = lane + 32 * q;
            m[q] = C[row * CSTRIDE + col] * inv;
            float f = bits_to_unit(rbits32(kv0, kv1, base_i + (uint32_t)col));
            float u = fmaxf(lo, fmaf(f, 2.0f, lo));
            v[q] = 1.41421356f * erfinv_f(u);
            dot = fmaf(m[q], v[q], dot);
        }
        #pragma unroll
        for (int s = 16; s; s >>= 1) dot += __shfl_xor_sync(0xffffffffu, dot, s);
        float o[4];
        float n2 = 0.0f;
        #pragma unroll
        for (int q = 0; q < 4; ++q) {
            o[q] = v[q] - m[q] * dot;
            n2 = fmaf(o[q], o[q], n2);
        }
        #pragma unroll
        for (int s = 16; s; s >>= 1) n2 += __shfl_xor_sync(0xffffffffu, n2, s);
        float invn = 1.0f / sqrtf(n2);
        float w = WM[row];
        float s1 = sqrtf(1.0f - w * w);
        #pragma unroll
        for (int q = 0; q < 4; ++q)
            out[OUT_VECS + (m0 + (size_t)row) * 128 + lane + 32 * q]
                = o[q] * invn * s1 + m[q] * w;
    }
}

extern "C" void kernel_launch(void* const* d_in, const int* in_sizes, int n_in,
                              void* d_out, int out_size) {
    const float* lat_code = (const float*)d_in[0];
    const float* W_mu     = (const float*)d_in[1];
    const float* b_mu     = (const float*)d_in[2];
    const float* kld      = (const float*)d_in[3];
    float* out = (float*)d_out;

    // Host-side threefry key chains (partitionable semantics)
    uint32_t f0, f1;
    tf2x32(0u, 42u, 0u, 0u, f0, f1);
    uint32_t kw0, kw1, kv0, kv1;
    tf2x32(f0, f1, 0u, 0u, kw0, kw1);
    tf2x32(f0, f1, 0u, 1u, kv0, kv1);

    WKeys K;
    uint32_t c0 = kw0, c1 = kw1;
    for (int t = 0; t < NITER; ++t) {
        uint32_t n0, n1, k1a, k1b, k2a, k2b;
        tf2x32(c0, c1, 0u, 0u, n0, n1);
        tf2x32(c0, c1, 0u, 1u, k1a, k1b);
        tf2x32(c0, c1, 0u, 2u, k2a, k2b);
        tf2x32(k1a, k1b, 0u, 0u, K.ka[t][0], K.ka[t][1]);
        tf2x32(k1a, k1b, 0u, 1u, K.kb[t][0], K.kb[t][1]);
        K.ku[t][0] = k2a; K.ku[t][1] = k2b;
        c0 = n0; c1 = n1;
    }

    double dd = 127.0, kap = 1.0;
    double bb = dd / (sqrt(4.0 * kap * kap + dd * dd) + 2.0 * kap);
    double xx = (1.0 - bb) / (1.0 + bb);
    double cc = kap * xx + dd * log(1.0 - xx * xx);
    float opb = (float)(1.0 + bb), omb = (float)(1.0 - bb);
    float xf = (float)xx, cf = (float)cc;

    cudaFuncSetAttribute(gemm_tc_kernel,
                         cudaFuncAttributeMaxDynamicSharedMemorySize, SM_TOTAL);

    // Fork-join: sample_w runs concurrent with w_split; join before fused GEMM
    // (the GEMM epilogue reads g_w).
    cudaStream_t s2;
    cudaEvent_t e_fork, e_join;
    bool forked = (cudaStreamCreateWithFlags(&s2, cudaStreamNonBlocking) == cudaSuccess) &&
                  (cudaEventCreateWithFlags(&e_fork, cudaEventDisableTiming) == cudaSuccess) &&
                  (cudaEventCreateWithFlags(&e_join, cudaEventDisableTiming) == cudaSuccess);

    if (forked) {
        cudaEventRecord(e_fork, 0);
        cudaStreamWaitEvent(s2, e_fork, 0);
        sample_w_kernel<<<B_ROWS / 256, 256, 0, s2>>>(K, opb, omb, xf, cf, kld, out);
        cudaEventRecord(e_join, s2);

        w_split_kernel2<<<128, 256>>>(W_mu);

        cudaStreamWaitEvent(0, e_join, 0);
        gemm_tc_kernel<<<B_ROWS / 128, 256, SM_TOTAL>>>(lat_code, b_mu, out, kv0, kv1);

        cudaEventDestroy(e_fork);
        cudaEventDestroy(e_join);
        cudaStreamDestroy(s2);
    } else {
        w_split_kernel2<<<128, 256>>>(W_mu);
        sample_w_kernel<<<B_ROWS / 256, 256>>>(K, opb, omb, xf, cf, kld, out);
        gemm_tc_kernel<<<B_ROWS / 128, 256, SM_TOTAL>>>(lat_code, b_mu, out, kv0, kv1);
    }
}